// round 9
// baseline (speedup 1.0000x reference)
#include <cuda_runtime.h>
#include <cuda_fp16.h>

#define NN 100000
#define EE 1600000
#define SCAN_NB 196     // ceil(NN/512)
#define GEMM_NB 782     // ceil(NN/128)
#define HIST_NB 6250    // ceil(EE/256)

// ---------------- scratch (device globals; no allocation) ----------------
__device__ __align__(256) __half g_feat1h[NN * 128]; // layer1 features fp16 [N][H=4][D=32]
__device__ __align__(16)  float g_el1[NN * 4];
__device__ __align__(16)  float g_er1[NN * 4];
__device__ float g_h[NN * 32];        // mid features after mean+relu (fp32)
__device__ __align__(16) float g_feat2[NN * 16];
__device__ float g_el2[NN];
__device__ float g_er2[NN];
__device__ int   g_rowptr[NN + 1];
__device__ int   g_cursor[NN];        // zero at start of each call (BSS / node2 cleanup)
__device__ int   g_csrsrc[EE];
__device__ unsigned long long g_desc[SCAN_NB];  // lookback: flag<<32 | value
__device__ int   g_scanctr;

// ---------------- f32x2 packed FMA (Blackwell) ----------------
__device__ __forceinline__ unsigned long long ffma2(unsigned long long a,
                                                    unsigned long long b,
                                                    unsigned long long c) {
    unsigned long long d;
    asm("fma.rn.f32x2 %0, %1, %2, %3;" : "=l"(d) : "l"(a), "l"(b), "l"(c));
    return d;
}

__device__ __forceinline__ void h8_to_f8(uint4 v, float* f) {
    float2 p;
    p = __half22float2(*reinterpret_cast<__half2*>(&v.x)); f[0] = p.x; f[1] = p.y;
    p = __half22float2(*reinterpret_cast<__half2*>(&v.y)); f[2] = p.x; f[3] = p.y;
    p = __half22float2(*reinterpret_cast<__half2*>(&v.z)); f[4] = p.x; f[5] = p.y;
    p = __half22float2(*reinterpret_cast<__half2*>(&v.w)); f[6] = p.x; f[7] = p.y;
}

// ---------------- fused GEMM1 (+coef epilogue) and dst histogram ----------
// blocks [0, GEMM_NB): feat1h = x @ W1 (fp16 store) + el1/er1 epilogue.
// blocks [GEMM_NB, GEMM_NB+HIST_NB): histogram of dst into g_cursor.
__global__ void __launch_bounds__(256) gemm1_hist_kernel(
        const float* __restrict__ x, const float* __restrict__ W,
        const float* __restrict__ al1, const float* __restrict__ ar1,
        const int* __restrict__ dst) {
    __shared__ union SMem {
        struct { float As[16][128]; float Bs[16][128]; } mm;
        float red[2][16][129];
    } sm;

    if (blockIdx.x >= GEMM_NB) {
        int e = (blockIdx.x - GEMM_NB) * 256 + threadIdx.x;
        if (e < EE) atomicAdd(&g_cursor[dst[e]], 1);
        return;
    }

    int tid = threadIdx.x;
    int row0 = blockIdx.x * 128;
    int tr = tid >> 4;       // 0..15 row group (8 rows each)
    int tc = tid & 15;       // 0..15 col group

    unsigned long long acc[8][4];
#pragma unroll
    for (int i = 0; i < 8; i++)
#pragma unroll
        for (int j = 0; j < 4; j++) acc[i][j] = 0ULL;

    for (int k0 = 0; k0 < 128; k0 += 16) {
#pragma unroll
        for (int q = 0; q < 2; q++) {
            int f = tid * 2 + q;                 // 0..511
            int r = f >> 2, c4 = (f & 3) << 2;
            int grow = row0 + r;
            float4 v = make_float4(0.f, 0.f, 0.f, 0.f);
            if (grow < NN) v = *(const float4*)&x[grow * 128 + k0 + c4];
            sm.mm.As[c4 + 0][r] = v.x; sm.mm.As[c4 + 1][r] = v.y;
            sm.mm.As[c4 + 2][r] = v.z; sm.mm.As[c4 + 3][r] = v.w;
            int kr = f >> 5, c8 = (f & 31) << 2;
            float4 wv = *(const float4*)&W[(k0 + kr) * 128 + c8];
            *(float4*)&sm.mm.Bs[kr][c8] = wv;
        }
        __syncthreads();
#pragma unroll
        for (int kk = 0; kk < 16; kk++) {
            unsigned long long b2[4];
#pragma unroll
            for (int j = 0; j < 4; j++)
                b2[j] = *(const unsigned long long*)&sm.mm.Bs[kk][tc * 2 + j * 32];
#pragma unroll
            for (int i = 0; i < 8; i++) {
                float a = sm.mm.As[kk][tr * 8 + i];
                unsigned long long a2;
                asm("mov.b64 %0, {%1, %2};" : "=l"(a2) : "f"(a), "f"(a));
#pragma unroll
                for (int j = 0; j < 4; j++) acc[i][j] = ffma2(a2, b2[j], acc[i][j]);
            }
        }
        __syncthreads();
    }
    // store features as fp16 (half2 per f32x2 accumulator)
#pragma unroll
    for (int i = 0; i < 8; i++) {
        int grow = row0 + tr * 8 + i;
        if (grow < NN) {
#pragma unroll
            for (int j = 0; j < 4; j++) {
                float lo, hi;
                asm("mov.b64 {%0, %1}, %2;" : "=f"(lo), "=f"(hi) : "l"(acc[i][j]));
                *(__half2*)&g_feat1h[grow * 128 + tc * 2 + j * 32] =
                    __floats2half2_rn(lo, hi);
            }
        }
    }
    // fused coefficients: per head j, partial dots then 16-lane smem reduce
#pragma unroll
    for (int j = 0; j < 4; j++) {
        float alo = al1[j * 32 + tc * 2], ahi = al1[j * 32 + tc * 2 + 1];
        float rlo = ar1[j * 32 + tc * 2], rhi = ar1[j * 32 + tc * 2 + 1];
        __syncthreads();
#pragma unroll
        for (int i = 0; i < 8; i++) {
            float lo, hi;
            asm("mov.b64 {%0, %1}, %2;" : "=f"(lo), "=f"(hi) : "l"(acc[i][j]));
            sm.red[0][tc][tr * 8 + i] = lo * alo + hi * ahi;
            sm.red[1][tc][tr * 8 + i] = lo * rlo + hi * rhi;
        }
        __syncthreads();
        if (tid < 128) {
            int row = tid;
            float se = 0.f, sr = 0.f;
#pragma unroll
            for (int c = 0; c < 16; c++) {
                se += sm.red[0][c][row];
                sr += sm.red[1][c][row];
            }
            int grow = row0 + row;
            if (grow < NN) {
                g_el1[grow * 4 + j] = se;
                g_er1[grow * 4 + j] = sr;
            }
        }
    }
}

// ---------------- single-pass exclusive scan (decoupled lookback) ---------
__global__ void __launch_bounds__(256) scan_kernel() {
    __shared__ int sh[256];
    __shared__ int s_bid;
    __shared__ int s_prefix;
    int t = threadIdx.x;
    if (t == 0) s_bid = atomicAdd(&g_scanctr, 1);
    __syncthreads();
    int b = s_bid;
    if (t == 0 && b == 0) g_rowptr[NN] = EE;
    int i0 = b * 512 + 2 * t;
    int c0 = (i0 < NN) ? g_cursor[i0] : 0;
    int c1 = (i0 + 1 < NN) ? g_cursor[i0 + 1] : 0;
    int local = c0 + c1;
    sh[t] = local;
    __syncthreads();
    for (int o = 1; o < 256; o <<= 1) {
        int v = (t >= o) ? sh[t - o] : 0;
        __syncthreads();
        sh[t] += v;
        __syncthreads();
    }
    int total = sh[255];
    if (t == 0) {
        if (b == 0) {
            *(volatile unsigned long long*)&g_desc[0] =
                (2ULL << 32) | (unsigned long long)(unsigned)total;
            s_prefix = 0;
        } else {
            *(volatile unsigned long long*)&g_desc[b] =
                (1ULL << 32) | (unsigned long long)(unsigned)total;
            int prefix = 0;
            int j = b - 1;
            while (true) {
                unsigned long long dsc;
                do { dsc = *(volatile unsigned long long*)&g_desc[j]; } while ((dsc >> 32) == 0ULL);
                prefix += (int)(unsigned)dsc;
                if ((dsc >> 32) == 2ULL) break;
                j--;
            }
            *(volatile unsigned long long*)&g_desc[b] =
                (2ULL << 32) | (unsigned long long)(unsigned)(prefix + total);
            s_prefix = prefix;
        }
    }
    __syncthreads();
    int off = s_prefix + sh[t] - local;
    if (i0 < NN)     { g_rowptr[i0] = off;          g_cursor[i0] = off; }
    if (i0 + 1 < NN) { g_rowptr[i0 + 1] = off + c0; g_cursor[i0 + 1] = off + c0; }
}

// ---------------- scatter edges into CSR ----------------
__global__ void scatter_kernel(const int* __restrict__ src, const int* __restrict__ dst) {
    int e = blockIdx.x * 256 + threadIdx.x;
    if (e < EE) {
        int d = dst[e];
        int slot = atomicAdd(&g_cursor[d], 1);
        g_csrsrc[slot] = src[e];
    }
}

// ---------------- layer 1 node aggregation ----------------
// block 128 = one dst node; warp h = head h.
// lane = g*4 + q: g = edge subgroup (8 edges in flight), q = feature quad
// (8 halves = 16B per lane). Single-pass softmax (no max; logits are small).
__global__ void __launch_bounds__(128) node1_kernel(const float* __restrict__ b1) {
    int n = blockIdx.x;
    int t = threadIdx.x;
    int h = t >> 5;
    int lane = t & 31;
    int g = lane >> 2, q = lane & 3;
    int beg = g_rowptr[n], end = g_rowptr[n + 1];
    int deg = end - beg;
    __shared__ int   sh_src[128];
    __shared__ float sh_w[4][128];
    __shared__ float sh_v[4][32];

    float4 ern = *(const float4*)&g_er1[n * 4];   // broadcast

    float a[8];
#pragma unroll
    for (int k = 0; k < 8; k++) a[k] = 0.f;
    float denom = 0.f;

    for (int c0 = 0; c0 < deg; c0 += 128) {
        int cnt = min(deg - c0, 128);
        __syncthreads();
        if (t < cnt) {
            int s = g_csrsrc[beg + c0 + t];
            sh_src[t] = s;
            float4 el = *(const float4*)&g_el1[s * 4];
            float e0 = el.x + ern.x; e0 = (e0 > 0.f) ? e0 : 0.2f * e0;
            float e1 = el.y + ern.y; e1 = (e1 > 0.f) ? e1 : 0.2f * e1;
            float e2 = el.z + ern.z; e2 = (e2 > 0.f) ? e2 : 0.2f * e2;
            float e3 = el.w + ern.w; e3 = (e3 > 0.f) ? e3 : 0.2f * e3;
            sh_w[0][t] = __expf(e0);
            sh_w[1][t] = __expf(e1);
            sh_w[2][t] = __expf(e2);
            sh_w[3][t] = __expf(e3);
        }
        __syncthreads();
        // per-head denom partials (lane-split)
        for (int j = lane; j < cnt; j += 32) denom += sh_w[h][j];
        // weighted feature gather: 8 edges in flight per warp iteration
        for (int j = 0; j < cnt; j += 8) {
            int e = j + g;
            if (e < cnt) {
                int s = sh_src[e];
                float w = sh_w[h][e];
                uint4 v = *(const uint4*)(g_feat1h + s * 128 + h * 32 + q * 8);
                float f[8];
                h8_to_f8(v, f);
#pragma unroll
                for (int k = 0; k < 8; k++) a[k] = fmaf(w, f[k], a[k]);
            }
        }
    }
    // reduce feature partials across the 8 edge subgroups (xor 4, 8, 16)
#pragma unroll
    for (int off = 4; off <= 16; off <<= 1)
#pragma unroll
        for (int k = 0; k < 8; k++)
            a[k] += __shfl_xor_sync(0xffffffffu, a[k], off);
    // denom over full warp
#pragma unroll
    for (int off = 16; off; off >>= 1)
        denom += __shfl_xor_sync(0xffffffffu, denom, off);

    float dsafe = (denom == 0.f) ? 1.f : denom;
    if (g == 0) {   // lanes 0..3 hold final feature sums
#pragma unroll
        for (int k = 0; k < 8; k++)
            sh_v[h][q * 8 + k] = a[k] / dsafe + b1[h * 32 + q * 8 + k];
    }
    __syncthreads();
    if (t < 32) {
        float mn = 0.25f * (sh_v[0][t] + sh_v[1][t] + sh_v[2][t] + sh_v[3][t]);
        g_h[n * 32 + t] = fmaxf(mn, 0.f);
    }
}

// ---------------- GEMM2 + coefficients layer 2 ----------------
__global__ void gemm2_kernel(const float* __restrict__ W2,
                             const float* __restrict__ al2,
                             const float* __restrict__ ar2) {
    __shared__ float sW[32 * 16];
    int t = threadIdx.x;
    for (int i = t; i < 512; i += 256) sW[i] = W2[i];
    __syncthreads();
    int warp = t >> 5, lane = t & 31;
    int g = lane >> 4, c = lane & 15;
    int n = (blockIdx.x * 8 + warp) * 2 + g;
    if (n >= NN) return;
    const float* hrow = g_h + n * 32;
    float acc = 0.f;
#pragma unroll
    for (int k = 0; k < 32; k++) acc = fmaf(hrow[k], sW[k * 16 + c], acc);
    g_feat2[n * 16 + c] = acc;
    float pe = acc * al2[c];
    float pr = acc * ar2[c];
#pragma unroll
    for (int o = 8; o; o >>= 1) {
        pe += __shfl_xor_sync(0xffffffffu, pe, o);
        pr += __shfl_xor_sync(0xffffffffu, pr, o);
    }
    if (c == 0) { g_el2[n] = pe; g_er2[n] = pr; }
}

// ---------------- layer 2 node aggregation + state cleanup ----------------
// block 128 = 4 warps; warp = one dst node. lane = g*4 + q: g = edge subgroup
// (8 edges in flight), q = feature quad (float4 = 16B).
// Tail: restore g_cursor/g_desc/g_scanctr to zero for the next call.
__global__ void __launch_bounds__(128) node2_kernel(const float* __restrict__ b2,
                                                    float* __restrict__ out) {
    // cleanup (state must equal BSS-zero initial condition after every call)
    int gi = blockIdx.x * 128 + threadIdx.x;
    if (gi < NN) g_cursor[gi] = 0;
    if (gi < SCAN_NB) g_desc[gi] = 0ULL;
    if (gi == 0) g_scanctr = 0;

    int wid = threadIdx.x >> 5;
    int lane = threadIdx.x & 31;
    int n = blockIdx.x * 4 + wid;
    if (n >= NN) return;
    int g = lane >> 2, q = lane & 3;
    int beg = g_rowptr[n], end = g_rowptr[n + 1];
    int deg = end - beg;
    float er_n = g_er2[n];
    __shared__ int   s2_src[4][32];
    __shared__ float s2_w[4][32];

    float a[4];
#pragma unroll
    for (int k = 0; k < 4; k++) a[k] = 0.f;
    float denom = 0.f;

    for (int c0 = 0; c0 < deg; c0 += 32) {
        int cnt = min(deg - c0, 32);
        if (lane < cnt) {
            int s = g_csrsrc[beg + c0 + lane];
            float e = g_el2[s] + er_n;
            e = (e > 0.f) ? e : 0.2f * e;
            float w = __expf(e);
            denom += w;
            s2_src[wid][lane] = s;
            s2_w[wid][lane] = w;
        }
        __syncwarp();
        for (int j = 0; j < cnt; j += 8) {
            int e = j + g;
            if (e < cnt) {
                int s = s2_src[wid][e];
                float w = s2_w[wid][e];
                float4 f = *(const float4*)&g_feat2[s * 16 + q * 4];
                a[0] = fmaf(w, f.x, a[0]); a[1] = fmaf(w, f.y, a[1]);
                a[2] = fmaf(w, f.z, a[2]); a[3] = fmaf(w, f.w, a[3]);
            }
        }
        __syncwarp();
    }
#pragma unroll
    for (int off = 4; off <= 16; off <<= 1)
#pragma unroll
        for (int k = 0; k < 4; k++)
            a[k] += __shfl_xor_sync(0xffffffffu, a[k], off);
#pragma unroll
    for (int off = 16; off; off >>= 1)
        denom += __shfl_xor_sync(0xffffffffu, denom, off);

    float dsafe = (denom == 0.f) ? 1.f : denom;
    if (g == 0) {   // lanes 0..3
#pragma unroll
        for (int k = 0; k < 4; k++)
            out[n * 16 + q * 4 + k] = a[k] / dsafe + b2[q * 4 + k];
    }
}

// ---------------- launch ----------------
// Launch index 3 == node1_kernel (profiler captures absolute index 3).
extern "C" void kernel_launch(void* const* d_in, const int* in_sizes, int n_in,
                              void* d_out, int out_size) {
    const float* x   = (const float*)d_in[0];
    const int*   src = (const int*)  d_in[1];
    const int*   dst = (const int*)  d_in[2];
    const float* W1  = (const float*)d_in[3];
    const float* al1 = (const float*)d_in[4];
    const float* ar1 = (const float*)d_in[5];
    const float* b1  = (const float*)d_in[6];
    const float* W2  = (const float*)d_in[7];
    const float* al2 = (const float*)d_in[8];
    const float* ar2 = (const float*)d_in[9];
    const float* b2  = (const float*)d_in[10];
    float* out = (float*)d_out;

    gemm1_hist_kernel<<<GEMM_NB + HIST_NB, 256>>>(x, W1, al1, ar1, dst); // 0
    scan_kernel<<<SCAN_NB, 256>>>();                                     // 1
    scatter_kernel<<<HIST_NB, 256>>>(src, dst);                          // 2
    node1_kernel<<<NN, 128>>>(b1);                                       // 3  <-- profiled
    gemm2_kernel<<<(NN + 15) / 16, 256>>>(W2, al2, ar2);                 // 4
    node2_kernel<<<(NN + 3) / 4, 128>>>(b2, out);                        // 5
}

// round 11
// speedup vs baseline: 1.8174x; 1.8174x over previous
#include <cuda_runtime.h>

#define NN 100000
#define EE 1600000
#define SCAN_NB 196     // ceil(NN/512)
#define GEMM_NB 782     // ceil(NN/128)
#define HIST_NB 6250    // ceil(EE/256)

// ---------------- scratch (device globals; no allocation) ----------------
__device__ __align__(256) float g_feat1[NN * 128]; // layer1 features [N][H=4][D=32]
__device__ __align__(16)  float g_el1[NN * 4];
__device__ __align__(16)  float g_er1[NN * 4];
__device__ float g_h[NN * 32];        // mid features after mean+relu
__device__ __align__(16) float g_feat2[NN * 16];
__device__ float g_el2[NN];
__device__ float g_er2[NN];
__device__ int   g_rowptr[NN + 1];
__device__ int   g_cursor[NN];        // zero at start of each call (BSS / node2 cleanup)
__device__ int   g_csrsrc[EE];
__device__ unsigned long long g_desc[SCAN_NB];  // lookback: flag<<32 | value
__device__ int   g_scanctr;

// ---------------- f32x2 packed FMA (Blackwell) ----------------
__device__ __forceinline__ unsigned long long ffma2(unsigned long long a,
                                                    unsigned long long b,
                                                    unsigned long long c) {
    unsigned long long d;
    asm("fma.rn.f32x2 %0, %1, %2, %3;" : "=l"(d) : "l"(a), "l"(b), "l"(c));
    return d;
}

// ---------------- fused GEMM1 (+coef epilogue) and dst histogram ----------
__global__ void __launch_bounds__(256) gemm1_hist_kernel(
        const float* __restrict__ x, const float* __restrict__ W,
        const float* __restrict__ al1, const float* __restrict__ ar1,
        const int* __restrict__ dst) {
    __shared__ union SMem {
        struct { float As[16][128]; float Bs[16][128]; } mm;
        float red[2][16][129];
    } sm;

    if (blockIdx.x >= GEMM_NB) {
        int e = (blockIdx.x - GEMM_NB) * 256 + threadIdx.x;
        if (e < EE) atomicAdd(&g_cursor[dst[e]], 1);
        return;
    }

    int tid = threadIdx.x;
    int row0 = blockIdx.x * 128;
    int tr = tid >> 4;       // 0..15 row group (8 rows each)
    int tc = tid & 15;       // 0..15 col group

    unsigned long long acc[8][4];
#pragma unroll
    for (int i = 0; i < 8; i++)
#pragma unroll
        for (int j = 0; j < 4; j++) acc[i][j] = 0ULL;

    for (int k0 = 0; k0 < 128; k0 += 16) {
#pragma unroll
        for (int q = 0; q < 2; q++) {
            int f = tid * 2 + q;                 // 0..511
            int r = f >> 2, c4 = (f & 3) << 2;
            int grow = row0 + r;
            float4 v = make_float4(0.f, 0.f, 0.f, 0.f);
            if (grow < NN) v = *(const float4*)&x[grow * 128 + k0 + c4];
            sm.mm.As[c4 + 0][r] = v.x; sm.mm.As[c4 + 1][r] = v.y;
            sm.mm.As[c4 + 2][r] = v.z; sm.mm.As[c4 + 3][r] = v.w;
            int kr = f >> 5, c8 = (f & 31) << 2;
            float4 wv = *(const float4*)&W[(k0 + kr) * 128 + c8];
            *(float4*)&sm.mm.Bs[kr][c8] = wv;
        }
        __syncthreads();
#pragma unroll
        for (int kk = 0; kk < 16; kk++) {
            unsigned long long b2[4];
#pragma unroll
            for (int j = 0; j < 4; j++)
                b2[j] = *(const unsigned long long*)&sm.mm.Bs[kk][tc * 2 + j * 32];
#pragma unroll
            for (int i = 0; i < 8; i++) {
                float a = sm.mm.As[kk][tr * 8 + i];
                unsigned long long a2;
                asm("mov.b64 %0, {%1, %2};" : "=l"(a2) : "f"(a), "f"(a));
#pragma unroll
                for (int j = 0; j < 4; j++) acc[i][j] = ffma2(a2, b2[j], acc[i][j]);
            }
        }
        __syncthreads();
    }
    // store features (fp32)
#pragma unroll
    for (int i = 0; i < 8; i++) {
        int grow = row0 + tr * 8 + i;
        if (grow < NN) {
#pragma unroll
            for (int j = 0; j < 4; j++)
                *(unsigned long long*)&g_feat1[grow * 128 + tc * 2 + j * 32] = acc[i][j];
        }
    }
    // fused coefficients: per head j, partial dots then 16-lane smem reduce
#pragma unroll
    for (int j = 0; j < 4; j++) {
        float alo = al1[j * 32 + tc * 2], ahi = al1[j * 32 + tc * 2 + 1];
        float rlo = ar1[j * 32 + tc * 2], rhi = ar1[j * 32 + tc * 2 + 1];
        __syncthreads();
#pragma unroll
        for (int i = 0; i < 8; i++) {
            float lo, hi;
            asm("mov.b64 {%0, %1}, %2;" : "=f"(lo), "=f"(hi) : "l"(acc[i][j]));
            sm.red[0][tc][tr * 8 + i] = lo * alo + hi * ahi;
            sm.red[1][tc][tr * 8 + i] = lo * rlo + hi * rhi;
        }
        __syncthreads();
        if (tid < 128) {
            int row = tid;
            float se = 0.f, sr = 0.f;
#pragma unroll
            for (int c = 0; c < 16; c++) {
                se += sm.red[0][c][row];
                sr += sm.red[1][c][row];
            }
            int grow = row0 + row;
            if (grow < NN) {
                g_el1[grow * 4 + j] = se;
                g_er1[grow * 4 + j] = sr;
            }
        }
    }
}

// ---------------- single-pass exclusive scan (decoupled lookback) ---------
__global__ void __launch_bounds__(256) scan_kernel() {
    __shared__ int sh[256];
    __shared__ int s_bid;
    __shared__ int s_prefix;
    int t = threadIdx.x;
    if (t == 0) s_bid = atomicAdd(&g_scanctr, 1);
    __syncthreads();
    int b = s_bid;
    if (t == 0 && b == 0) g_rowptr[NN] = EE;
    int i0 = b * 512 + 2 * t;
    int c0 = (i0 < NN) ? g_cursor[i0] : 0;
    int c1 = (i0 + 1 < NN) ? g_cursor[i0 + 1] : 0;
    int local = c0 + c1;
    sh[t] = local;
    __syncthreads();
    for (int o = 1; o < 256; o <<= 1) {
        int v = (t >= o) ? sh[t - o] : 0;
        __syncthreads();
        sh[t] += v;
        __syncthreads();
    }
    int total = sh[255];
    if (t == 0) {
        if (b == 0) {
            *(volatile unsigned long long*)&g_desc[0] =
                (2ULL << 32) | (unsigned long long)(unsigned)total;
            s_prefix = 0;
        } else {
            *(volatile unsigned long long*)&g_desc[b] =
                (1ULL << 32) | (unsigned long long)(unsigned)total;
            int prefix = 0;
            int j = b - 1;
            while (true) {
                unsigned long long dsc;
                do { dsc = *(volatile unsigned long long*)&g_desc[j]; } while ((dsc >> 32) == 0ULL);
                prefix += (int)(unsigned)dsc;
                if ((dsc >> 32) == 2ULL) break;
                j--;
            }
            *(volatile unsigned long long*)&g_desc[b] =
                (2ULL << 32) | (unsigned long long)(unsigned)(prefix + total);
            s_prefix = prefix;
        }
    }
    __syncthreads();
    int off = s_prefix + sh[t] - local;
    if (i0 < NN)     { g_rowptr[i0] = off;          g_cursor[i0] = off; }
    if (i0 + 1 < NN) { g_rowptr[i0 + 1] = off + c0; g_cursor[i0 + 1] = off + c0; }
}

// ---------------- scatter edges into CSR ----------------
__global__ void scatter_kernel(const int* __restrict__ src, const int* __restrict__ dst) {
    int e = blockIdx.x * 256 + threadIdx.x;
    if (e < EE) {
        int d = dst[e];
        int slot = atomicAdd(&g_cursor[d], 1);
        g_csrsrc[slot] = src[e];
    }
}

// ---------------- layer 1 node aggregation ----------------
// WARP PER NODE, all 4 heads simultaneously.
// lane = h*8 + fq (h = lane>>3 head, fq = lane&7 feature quad).
// One LDG.128 per edge fetches the whole 512B feature row, coalesced.
__global__ void __launch_bounds__(256) node1_kernel(const float* __restrict__ b1) {
    int wid = threadIdx.x >> 5;
    int lane = threadIdx.x & 31;
    int n = blockIdx.x * 8 + wid;
    if (n >= NN) return;
    int h = lane >> 3;

    __shared__ int   sh_src[8][32];
    __shared__ float sh_w[8][4][32];

    int beg = g_rowptr[n], deg = g_rowptr[n + 1] - beg;
    float4 ern = *(const float4*)&g_er1[n * 4];

    float4 dsum = make_float4(0.f, 0.f, 0.f, 0.f);
    float4 acc  = make_float4(0.f, 0.f, 0.f, 0.f);

    for (int c0 = 0; c0 < deg; c0 += 32) {
        int cnt = min(deg - c0, 32);
        if (lane < cnt) {
            int s = g_csrsrc[beg + c0 + lane];
            sh_src[wid][lane] = s;
            float4 el = *(const float4*)&g_el1[s * 4];
            float e0 = el.x + ern.x; e0 = (e0 > 0.f) ? e0 : 0.2f * e0;
            float e1 = el.y + ern.y; e1 = (e1 > 0.f) ? e1 : 0.2f * e1;
            float e2 = el.z + ern.z; e2 = (e2 > 0.f) ? e2 : 0.2f * e2;
            float e3 = el.w + ern.w; e3 = (e3 > 0.f) ? e3 : 0.2f * e3;
            float w0 = __expf(e0), w1 = __expf(e1), w2 = __expf(e2), w3 = __expf(e3);
            dsum.x += w0; dsum.y += w1; dsum.z += w2; dsum.w += w3;
            sh_w[wid][0][lane] = w0; sh_w[wid][1][lane] = w1;
            sh_w[wid][2][lane] = w2; sh_w[wid][3][lane] = w3;
        }
        __syncwarp();
        // gather: 1 LDG.128 + 4 FMA per edge (covers all 4 heads), unroll 4
        int e = 0;
        for (; e + 4 <= cnt; e += 4) {
            int s0 = sh_src[wid][e],     s1 = sh_src[wid][e + 1];
            int s2 = sh_src[wid][e + 2], s3 = sh_src[wid][e + 3];
            float w0 = sh_w[wid][h][e],     w1 = sh_w[wid][h][e + 1];
            float w2 = sh_w[wid][h][e + 2], w3 = sh_w[wid][h][e + 3];
            float4 f0 = *(const float4*)&g_feat1[s0 * 128 + lane * 4];
            float4 f1 = *(const float4*)&g_feat1[s1 * 128 + lane * 4];
            float4 f2 = *(const float4*)&g_feat1[s2 * 128 + lane * 4];
            float4 f3 = *(const float4*)&g_feat1[s3 * 128 + lane * 4];
            acc.x = fmaf(w0, f0.x, acc.x); acc.y = fmaf(w0, f0.y, acc.y);
            acc.z = fmaf(w0, f0.z, acc.z); acc.w = fmaf(w0, f0.w, acc.w);
            acc.x = fmaf(w1, f1.x, acc.x); acc.y = fmaf(w1, f1.y, acc.y);
            acc.z = fmaf(w1, f1.z, acc.z); acc.w = fmaf(w1, f1.w, acc.w);
            acc.x = fmaf(w2, f2.x, acc.x); acc.y = fmaf(w2, f2.y, acc.y);
            acc.z = fmaf(w2, f2.z, acc.z); acc.w = fmaf(w2, f2.w, acc.w);
            acc.x = fmaf(w3, f3.x, acc.x); acc.y = fmaf(w3, f3.y, acc.y);
            acc.z = fmaf(w3, f3.z, acc.z); acc.w = fmaf(w3, f3.w, acc.w);
        }
        for (; e < cnt; e++) {
            int s = sh_src[wid][e];
            float w = sh_w[wid][h][e];
            float4 f = *(const float4*)&g_feat1[s * 128 + lane * 4];
            acc.x = fmaf(w, f.x, acc.x); acc.y = fmaf(w, f.y, acc.y);
            acc.z = fmaf(w, f.z, acc.z); acc.w = fmaf(w, f.w, acc.w);
        }
        __syncwarp();
    }

    // reduce per-head denominators across the warp (float4 butterfly)
#pragma unroll
    for (int o = 16; o; o >>= 1) {
        dsum.x += __shfl_xor_sync(0xffffffffu, dsum.x, o);
        dsum.y += __shfl_xor_sync(0xffffffffu, dsum.y, o);
        dsum.z += __shfl_xor_sync(0xffffffffu, dsum.z, o);
        dsum.w += __shfl_xor_sync(0xffffffffu, dsum.w, o);
    }
    float denom = (h == 0) ? dsum.x : (h == 1) ? dsum.y : (h == 2) ? dsum.z : dsum.w;
    float inv = 1.f / ((denom == 0.f) ? 1.f : denom);

    float4 bv = ((const float4*)b1)[lane];   // b1[h*32 + fq*4 .. +3] == b1[lane*4..]
    float4 v;
    v.x = acc.x * inv + bv.x;
    v.y = acc.y * inv + bv.y;
    v.z = acc.z * inv + bv.z;
    v.w = acc.w * inv + bv.w;

    // mean over heads: xor 8 then 16 sums the 4 head lanes at fixed fq
#pragma unroll
    for (int o = 8; o <= 16; o <<= 1) {
        v.x += __shfl_xor_sync(0xffffffffu, v.x, o);
        v.y += __shfl_xor_sync(0xffffffffu, v.y, o);
        v.z += __shfl_xor_sync(0xffffffffu, v.z, o);
        v.w += __shfl_xor_sync(0xffffffffu, v.w, o);
    }
    if (lane < 8) {
        float4 o4;
        o4.x = fmaxf(0.25f * v.x, 0.f);
        o4.y = fmaxf(0.25f * v.y, 0.f);
        o4.z = fmaxf(0.25f * v.z, 0.f);
        o4.w = fmaxf(0.25f * v.w, 0.f);
        *(float4*)&g_h[n * 32 + lane * 4] = o4;
    }
}

// ---------------- GEMM2 + coefficients layer 2 ----------------
__global__ void gemm2_kernel(const float* __restrict__ W2,
                             const float* __restrict__ al2,
                             const float* __restrict__ ar2) {
    __shared__ float sW[32 * 16];
    int t = threadIdx.x;
    for (int i = t; i < 512; i += 256) sW[i] = W2[i];
    __syncthreads();
    int warp = t >> 5, lane = t & 31;
    int g = lane >> 4, c = lane & 15;
    int n = (blockIdx.x * 8 + warp) * 2 + g;
    if (n >= NN) return;
    const float* hrow = g_h + n * 32;
    float acc = 0.f;
#pragma unroll
    for (int k = 0; k < 32; k++) acc = fmaf(hrow[k], sW[k * 16 + c], acc);
    g_feat2[n * 16 + c] = acc;
    float pe = acc * al2[c];
    float pr = acc * ar2[c];
#pragma unroll
    for (int o = 8; o; o >>= 1) {
        pe += __shfl_xor_sync(0xffffffffu, pe, o);
        pr += __shfl_xor_sync(0xffffffffu, pr, o);
    }
    if (c == 0) { g_el2[n] = pe; g_er2[n] = pr; }
}

// ---------------- layer 2 node aggregation + state cleanup ----------------
// Proven R3 structure: warp per node, edge streams split across lane halves.
__global__ void __launch_bounds__(128) node2_kernel(const float* __restrict__ b2,
                                                    float* __restrict__ out) {
    // cleanup (state must equal BSS-zero initial condition after every call)
    int gi = blockIdx.x * 128 + threadIdx.x;
    if (gi < NN) g_cursor[gi] = 0;
    if (gi < SCAN_NB) g_desc[gi] = 0ULL;
    if (gi == 0) g_scanctr = 0;

    int wid = threadIdx.x >> 5;
    int lane = threadIdx.x & 31;
    int n = blockIdx.x * 4 + wid;
    if (n >= NN) return;
    int beg = g_rowptr[n], end = g_rowptr[n + 1];
    int deg = end - beg;
    float er_n = g_er2[n];
    int p = lane >> 4, d = lane & 15;

    float denom = 0.f, acc = 0.f;
    for (int c0 = 0; c0 < deg; c0 += 32) {
        int cnt = min(deg - c0, 32);
        int s = 0; float w = 0.f;
        if (lane < cnt) {
            s = g_csrsrc[beg + c0 + lane];
            float e = g_el2[s] + er_n;
            e = (e > 0.f) ? e : 0.2f * e;
            w = __expf(e);
            denom += w;
        }
        for (int j2 = 0; j2 < cnt; j2 += 2) {
            int j = j2 + p;
            int jj = (j < cnt) ? j : 0;
            float wj = __shfl_sync(0xffffffffu, w, jj);
            int   sj = __shfl_sync(0xffffffffu, s, jj);
            if (j < cnt) acc = fmaf(wj, g_feat2[sj * 16 + d], acc);
        }
    }
#pragma unroll
    for (int o = 16; o; o >>= 1) denom += __shfl_xor_sync(0xffffffffu, denom, o);
    acc += __shfl_down_sync(0xffffffffu, acc, 16);
    float dsafe = (denom == 0.f) ? 1.f : denom;
    if (lane < 16) out[n * 16 + lane] = acc / dsafe + b2[lane];
}

// ---------------- launch ----------------
// Launch index 3 == node1_kernel (profiler captures absolute index 3).
extern "C" void kernel_launch(void* const* d_in, const int* in_sizes, int n_in,
                              void* d_out, int out_size) {
    const float* x   = (const float*)d_in[0];
    const int*   src = (const int*)  d_in[1];
    const int*   dst = (const int*)  d_in[2];
    const float* W1  = (const float*)d_in[3];
    const float* al1 = (const float*)d_in[4];
    const float* ar1 = (const float*)d_in[5];
    const float* b1  = (const float*)d_in[6];
    const float* W2  = (const float*)d_in[7];
    const float* al2 = (const float*)d_in[8];
    const float* ar2 = (const float*)d_in[9];
    const float* b2  = (const float*)d_in[10];
    float* out = (float*)d_out;

    gemm1_hist_kernel<<<GEMM_NB + HIST_NB, 256>>>(x, W1, al1, ar1, dst); // 0
    scan_kernel<<<SCAN_NB, 256>>>();                                     // 1
    scatter_kernel<<<HIST_NB, 256>>>(src, dst);                          // 2
    node1_kernel<<<(NN + 7) / 8, 256>>>(b1);                             // 3  <-- profiled
    gemm2_kernel<<<(NN + 15) / 16, 256>>>(W2, al2, ar2);                 // 4
    node2_kernel<<<(NN + 3) / 4, 128>>>(b2, out);                        // 5
}

// round 13
// speedup vs baseline: 1.8558x; 1.0212x over previous
#include <cuda_runtime.h>

#define NN 100000
#define EE 1600000
#define SCAN_NB 196     // ceil(NN/512)
#define GEMM_NB 782     // ceil(NN/128)
#define SCAT_NB 6250    // ceil(EE/256)
#define EHALF 800000

// ---------------- scratch (device globals; no allocation) ----------------
__device__ __align__(256) float g_feat1[NN * 128]; // layer1 features [N][H=4][D=32]
__device__ __align__(16)  float g_el1[NN * 4];
__device__ __align__(16)  float g_er1[NN * 4];
__device__ float g_h[NN * 32];        // mid features after mean+relu
__device__ __align__(16) float g_feat2[NN * 16];
__device__ float g_el2[NN];
__device__ float g_er2[NN];
__device__ int   g_rowptr[NN + 1];
__device__ int   g_cursor[NN];        // zero at start of each call (BSS / node2 cleanup)
__device__ int   g_csrsrc[EE];
__device__ unsigned long long g_desc[SCAN_NB];  // lookback: flag<<32 | value
__device__ int   g_scanctr;

// ---------------- f32x2 packed FMA (Blackwell) ----------------
__device__ __forceinline__ unsigned long long ffma2(unsigned long long a,
                                                    unsigned long long b,
                                                    unsigned long long c) {
    unsigned long long d;
    asm("fma.rn.f32x2 %0, %1, %2, %3;" : "=l"(d) : "l"(a), "l"(b), "l"(c));
    return d;
}

// ---------------- histogram of dst (two half-range launches) --------------
__global__ void hist_kernel(const int* __restrict__ dst, int base, int count) {
    int e = base + blockIdx.x * 256 + threadIdx.x;
    if (e < base + count) atomicAdd(&g_cursor[dst[e]], 1);
}

// ---------------- single-pass exclusive scan (decoupled lookback) ---------
__global__ void __launch_bounds__(256) scan_kernel() {
    __shared__ int sh[256];
    __shared__ int s_bid;
    __shared__ int s_prefix;
    int t = threadIdx.x;
    if (t == 0) s_bid = atomicAdd(&g_scanctr, 1);
    __syncthreads();
    int b = s_bid;
    if (t == 0 && b == 0) g_rowptr[NN] = EE;
    int i0 = b * 512 + 2 * t;
    int c0 = (i0 < NN) ? g_cursor[i0] : 0;
    int c1 = (i0 + 1 < NN) ? g_cursor[i0 + 1] : 0;
    int local = c0 + c1;
    sh[t] = local;
    __syncthreads();
    for (int o = 1; o < 256; o <<= 1) {
        int v = (t >= o) ? sh[t - o] : 0;
        __syncthreads();
        sh[t] += v;
        __syncthreads();
    }
    int total = sh[255];
    if (t == 0) {
        if (b == 0) {
            *(volatile unsigned long long*)&g_desc[0] =
                (2ULL << 32) | (unsigned long long)(unsigned)total;
            s_prefix = 0;
        } else {
            *(volatile unsigned long long*)&g_desc[b] =
                (1ULL << 32) | (unsigned long long)(unsigned)total;
            int prefix = 0;
            int j = b - 1;
            while (true) {
                unsigned long long dsc;
                do { dsc = *(volatile unsigned long long*)&g_desc[j]; } while ((dsc >> 32) == 0ULL);
                prefix += (int)(unsigned)dsc;
                if ((dsc >> 32) == 2ULL) break;
                j--;
            }
            *(volatile unsigned long long*)&g_desc[b] =
                (2ULL << 32) | (unsigned long long)(unsigned)(prefix + total);
            s_prefix = prefix;
        }
    }
    __syncthreads();
    int off = s_prefix + sh[t] - local;
    if (i0 < NN)     { g_rowptr[i0] = off;          g_cursor[i0] = off; }
    if (i0 + 1 < NN) { g_rowptr[i0 + 1] = off + c0; g_cursor[i0 + 1] = off + c0; }
}

// ---------------- fused GEMM1 (+coef epilogue) and CSR scatter ------------
// blocks [0, GEMM_NB): feat1 = x @ W1 + el1/er1 epilogue (FMA-bound).
// blocks [GEMM_NB, GEMM_NB+SCAT_NB): scatter edges into CSR (atomic-latency
// bound) — overlaps with the GEMM blocks on the same SMs.
__global__ void __launch_bounds__(256) gemm1_scatter_kernel(
        const float* __restrict__ x, const float* __restrict__ W,
        const float* __restrict__ al1, const float* __restrict__ ar1,
        const int* __restrict__ src, const int* __restrict__ dst) {
    __shared__ union SMem {
        struct { float As[16][128]; float Bs[16][128]; } mm;
        float red[2][16][129];
    } sm;

    if (blockIdx.x >= GEMM_NB) {
        int e = (blockIdx.x - GEMM_NB) * 256 + threadIdx.x;
        if (e < EE) {
            int d = dst[e];
            int slot = atomicAdd(&g_cursor[d], 1);
            g_csrsrc[slot] = src[e];
        }
        return;
    }

    int tid = threadIdx.x;
    int row0 = blockIdx.x * 128;
    int tr = tid >> 4;       // 0..15 row group (8 rows each)
    int tc = tid & 15;       // 0..15 col group

    unsigned long long acc[8][4];
#pragma unroll
    for (int i = 0; i < 8; i++)
#pragma unroll
        for (int j = 0; j < 4; j++) acc[i][j] = 0ULL;

    for (int k0 = 0; k0 < 128; k0 += 16) {
#pragma unroll
        for (int q = 0; q < 2; q++) {
            int f = tid * 2 + q;                 // 0..511
            int r = f >> 2, c4 = (f & 3) << 2;
            int grow = row0 + r;
            float4 v = make_float4(0.f, 0.f, 0.f, 0.f);
            if (grow < NN) v = *(const float4*)&x[grow * 128 + k0 + c4];
            sm.mm.As[c4 + 0][r] = v.x; sm.mm.As[c4 + 1][r] = v.y;
            sm.mm.As[c4 + 2][r] = v.z; sm.mm.As[c4 + 3][r] = v.w;
            int kr = f >> 5, c8 = (f & 31) << 2;
            float4 wv = *(const float4*)&W[(k0 + kr) * 128 + c8];
            *(float4*)&sm.mm.Bs[kr][c8] = wv;
        }
        __syncthreads();
#pragma unroll
        for (int kk = 0; kk < 16; kk++) {
            unsigned long long b2[4];
#pragma unroll
            for (int j = 0; j < 4; j++)
                b2[j] = *(const unsigned long long*)&sm.mm.Bs[kk][tc * 2 + j * 32];
#pragma unroll
            for (int i = 0; i < 8; i++) {
                float a = sm.mm.As[kk][tr * 8 + i];
                unsigned long long a2;
                asm("mov.b64 %0, {%1, %2};" : "=l"(a2) : "f"(a), "f"(a));
#pragma unroll
                for (int j = 0; j < 4; j++) acc[i][j] = ffma2(a2, b2[j], acc[i][j]);
            }
        }
        __syncthreads();
    }
    // store features (fp32)
#pragma unroll
    for (int i = 0; i < 8; i++) {
        int grow = row0 + tr * 8 + i;
        if (grow < NN) {
#pragma unroll
            for (int j = 0; j < 4; j++)
                *(unsigned long long*)&g_feat1[grow * 128 + tc * 2 + j * 32] = acc[i][j];
        }
    }
    // fused coefficients: per head j, partial dots then 16-lane smem reduce
#pragma unroll
    for (int j = 0; j < 4; j++) {
        float alo = al1[j * 32 + tc * 2], ahi = al1[j * 32 + tc * 2 + 1];
        float rlo = ar1[j * 32 + tc * 2], rhi = ar1[j * 32 + tc * 2 + 1];
        __syncthreads();
#pragma unroll
        for (int i = 0; i < 8; i++) {
            float lo, hi;
            asm("mov.b64 {%0, %1}, %2;" : "=f"(lo), "=f"(hi) : "l"(acc[i][j]));
            sm.red[0][tc][tr * 8 + i] = lo * alo + hi * ahi;
            sm.red[1][tc][tr * 8 + i] = lo * rlo + hi * rhi;
        }
        __syncthreads();
        if (tid < 128) {
            int row = tid;
            float se = 0.f, sr = 0.f;
#pragma unroll
            for (int c = 0; c < 16; c++) {
                se += sm.red[0][c][row];
                sr += sm.red[1][c][row];
            }
            int grow = row0 + row;
            if (grow < NN) {
                g_el1[grow * 4 + j] = se;
                g_er1[grow * 4 + j] = sr;
            }
        }
    }
}

// ---------------- layer 1 node aggregation ----------------
// WARP PER NODE, all 4 heads simultaneously.
// lane = h*8 + fq; one LDG.128 per edge fetches the whole 512B row, coalesced.
// launch_bounds(256, 5): cap regs ~48 -> 5 blocks/SM (was 52 regs, 4 blocks).
__global__ void __launch_bounds__(256, 5) node1_kernel(const float* __restrict__ b1) {
    int wid = threadIdx.x >> 5;
    int lane = threadIdx.x & 31;
    int n = blockIdx.x * 8 + wid;
    if (n >= NN) return;
    int h = lane >> 3;

    __shared__ int   sh_src[8][32];
    __shared__ float sh_w[8][4][32];

    int beg = g_rowptr[n], deg = g_rowptr[n + 1] - beg;
    float4 ern = *(const float4*)&g_er1[n * 4];

    float4 dsum = make_float4(0.f, 0.f, 0.f, 0.f);
    float4 acc  = make_float4(0.f, 0.f, 0.f, 0.f);

    for (int c0 = 0; c0 < deg; c0 += 32) {
        int cnt = min(deg - c0, 32);
        if (lane < cnt) {
            int s = g_csrsrc[beg + c0 + lane];
            sh_src[wid][lane] = s;
            float4 el = *(const float4*)&g_el1[s * 4];
            float e0 = el.x + ern.x; e0 = (e0 > 0.f) ? e0 : 0.2f * e0;
            float e1 = el.y + ern.y; e1 = (e1 > 0.f) ? e1 : 0.2f * e1;
            float e2 = el.z + ern.z; e2 = (e2 > 0.f) ? e2 : 0.2f * e2;
            float e3 = el.w + ern.w; e3 = (e3 > 0.f) ? e3 : 0.2f * e3;
            float w0 = __expf(e0), w1 = __expf(e1), w2 = __expf(e2), w3 = __expf(e3);
            dsum.x += w0; dsum.y += w1; dsum.z += w2; dsum.w += w3;
            sh_w[wid][0][lane] = w0; sh_w[wid][1][lane] = w1;
            sh_w[wid][2][lane] = w2; sh_w[wid][3][lane] = w3;
        }
        __syncwarp();
        int e = 0;
        for (; e + 4 <= cnt; e += 4) {
            int s0 = sh_src[wid][e],     s1 = sh_src[wid][e + 1];
            int s2 = sh_src[wid][e + 2], s3 = sh_src[wid][e + 3];
            float w0 = sh_w[wid][h][e],     w1 = sh_w[wid][h][e + 1];
            float w2 = sh_w[wid][h][e + 2], w3 = sh_w[wid][h][e + 3];
            float4 f0 = *(const float4*)&g_feat1[s0 * 128 + lane * 4];
            float4 f1 = *(const float4*)&g_feat1[s1 * 128 + lane * 4];
            float4 f2 = *(const float4*)&g_feat1[s2 * 128 + lane * 4];
            float4 f3 = *(const float4*)&g_feat1[s3 * 128 + lane * 4];
            acc.x = fmaf(w0, f0.x, acc.x); acc.y = fmaf(w0, f0.y, acc.y);
            acc.z = fmaf(w0, f0.z, acc.z); acc.w = fmaf(w0, f0.w, acc.w);
            acc.x = fmaf(w1, f1.x, acc.x); acc.y = fmaf(w1, f1.y, acc.y);
            acc.z = fmaf(w1, f1.z, acc.z); acc.w = fmaf(w1, f1.w, acc.w);
            acc.x = fmaf(w2, f2.x, acc.x); acc.y = fmaf(w2, f2.y, acc.y);
            acc.z = fmaf(w2, f2.z, acc.z); acc.w = fmaf(w2, f2.w, acc.w);
            acc.x = fmaf(w3, f3.x, acc.x); acc.y = fmaf(w3, f3.y, acc.y);
            acc.z = fmaf(w3, f3.z, acc.z); acc.w = fmaf(w3, f3.w, acc.w);
        }
        for (; e < cnt; e++) {
            int s = sh_src[wid][e];
            float w = sh_w[wid][h][e];
            float4 f = *(const float4*)&g_feat1[s * 128 + lane * 4];
            acc.x = fmaf(w, f.x, acc.x); acc.y = fmaf(w, f.y, acc.y);
            acc.z = fmaf(w, f.z, acc.z); acc.w = fmaf(w, f.w, acc.w);
        }
        __syncwarp();
    }

#pragma unroll
    for (int o = 16; o; o >>= 1) {
        dsum.x += __shfl_xor_sync(0xffffffffu, dsum.x, o);
        dsum.y += __shfl_xor_sync(0xffffffffu, dsum.y, o);
        dsum.z += __shfl_xor_sync(0xffffffffu, dsum.z, o);
        dsum.w += __shfl_xor_sync(0xffffffffu, dsum.w, o);
    }
    float denom = (h == 0) ? dsum.x : (h == 1) ? dsum.y : (h == 2) ? dsum.z : dsum.w;
    float inv = 1.f / ((denom == 0.f) ? 1.f : denom);

    float4 bv = ((const float4*)b1)[lane];
    float4 v;
    v.x = acc.x * inv + bv.x;
    v.y = acc.y * inv + bv.y;
    v.z = acc.z * inv + bv.z;
    v.w = acc.w * inv + bv.w;

    // mean over heads: xor 8 then 16 sums the 4 head lanes at fixed fq
#pragma unroll
    for (int o = 8; o <= 16; o <<= 1) {
        v.x += __shfl_xor_sync(0xffffffffu, v.x, o);
        v.y += __shfl_xor_sync(0xffffffffu, v.y, o);
        v.z += __shfl_xor_sync(0xffffffffu, v.z, o);
        v.w += __shfl_xor_sync(0xffffffffu, v.w, o);
    }
    if (lane < 8) {
        float4 o4;
        o4.x = fmaxf(0.25f * v.x, 0.f);
        o4.y = fmaxf(0.25f * v.y, 0.f);
        o4.z = fmaxf(0.25f * v.z, 0.f);
        o4.w = fmaxf(0.25f * v.w, 0.f);
        *(float4*)&g_h[n * 32 + lane * 4] = o4;
    }
}

// ---------------- GEMM2 + coefficients layer 2 ----------------
__global__ void gemm2_kernel(const float* __restrict__ W2,
                             const float* __restrict__ al2,
                             const float* __restrict__ ar2) {
    __shared__ float sW[32 * 16];
    int t = threadIdx.x;
    for (int i = t; i < 512; i += 256) sW[i] = W2[i];
    __syncthreads();
    int warp = t >> 5, lane = t & 31;
    int g = lane >> 4, c = lane & 15;
    int n = (blockIdx.x * 8 + warp) * 2 + g;
    if (n >= NN) return;
    const float* hrow = g_h + n * 32;
    float acc = 0.f;
#pragma unroll
    for (int k = 0; k < 32; k++) acc = fmaf(hrow[k], sW[k * 16 + c], acc);
    g_feat2[n * 16 + c] = acc;
    float pe = acc * al2[c];
    float pr = acc * ar2[c];
#pragma unroll
    for (int o = 8; o; o >>= 1) {
        pe += __shfl_xor_sync(0xffffffffu, pe, o);
        pr += __shfl_xor_sync(0xffffffffu, pr, o);
    }
    if (c == 0) { g_el2[n] = pe; g_er2[n] = pr; }
}

// ---------------- layer 2 node aggregation + state cleanup ----------------
__global__ void __launch_bounds__(128) node2_kernel(const float* __restrict__ b2,
                                                    float* __restrict__ out) {
    // cleanup (state must equal BSS-zero initial condition after every call)
    int gi = blockIdx.x * 128 + threadIdx.x;
    if (gi < NN) g_cursor[gi] = 0;
    if (gi < SCAN_NB) g_desc[gi] = 0ULL;
    if (gi == 0) g_scanctr = 0;

    int wid = threadIdx.x >> 5;
    int lane = threadIdx.x & 31;
    int n = blockIdx.x * 4 + wid;
    if (n >= NN) return;
    int beg = g_rowptr[n], end = g_rowptr[n + 1];
    int deg = end - beg;
    float er_n = g_er2[n];
    int p = lane >> 4, d = lane & 15;

    float denom = 0.f, acc = 0.f;
    for (int c0 = 0; c0 < deg; c0 += 32) {
        int cnt = min(deg - c0, 32);
        int s = 0; float w = 0.f;
        if (lane < cnt) {
            s = g_csrsrc[beg + c0 + lane];
            float e = g_el2[s] + er_n;
            e = (e > 0.f) ? e : 0.2f * e;
            w = __expf(e);
            denom += w;
        }
        for (int j2 = 0; j2 < cnt; j2 += 2) {
            int j = j2 + p;
            int jj = (j < cnt) ? j : 0;
            float wj = __shfl_sync(0xffffffffu, w, jj);
            int   sj = __shfl_sync(0xffffffffu, s, jj);
            if (j < cnt) acc = fmaf(wj, g_feat2[sj * 16 + d], acc);
        }
    }
#pragma unroll
    for (int o = 16; o; o >>= 1) denom += __shfl_xor_sync(0xffffffffu, denom, o);
    acc += __shfl_down_sync(0xffffffffu, acc, 16);
    float dsafe = (denom == 0.f) ? 1.f : denom;
    if (lane < 16) out[n * 16 + lane] = acc / dsafe + b2[lane];
}

// ---------------- launch ----------------
// Launch index 3 == gemm1_scatter_kernel (profiler captures absolute index 3).
extern "C" void kernel_launch(void* const* d_in, const int* in_sizes, int n_in,
                              void* d_out, int out_size) {
    const float* x   = (const float*)d_in[0];
    const int*   src = (const int*)  d_in[1];
    const int*   dst = (const int*)  d_in[2];
    const float* W1  = (const float*)d_in[3];
    const float* al1 = (const float*)d_in[4];
    const float* ar1 = (const float*)d_in[5];
    const float* b1  = (const float*)d_in[6];
    const float* W2  = (const float*)d_in[7];
    const float* al2 = (const float*)d_in[8];
    const float* ar2 = (const float*)d_in[9];
    const float* b2  = (const float*)d_in[10];
    float* out = (float*)d_out;

    hist_kernel<<<(EHALF + 255) / 256, 256>>>(dst, 0, EHALF);                 // 0
    hist_kernel<<<(EE - EHALF + 255) / 256, 256>>>(dst, EHALF, EE - EHALF);   // 1
    scan_kernel<<<SCAN_NB, 256>>>();                                          // 2
    gemm1_scatter_kernel<<<GEMM_NB + SCAT_NB, 256>>>(x, W1, al1, ar1, src, dst); // 3 <-- profiled
    node1_kernel<<<(NN + 7) / 8, 256>>>(b1);                                  // 4
    gemm2_kernel<<<(NN + 15) / 16, 256>>>(W2, al2, ar2);                      // 5
    node2_kernel<<<(NN + 3) / 4, 128>>>(b2, out);                             // 6
}